// round 16
// baseline (speedup 1.0000x reference)
#include <cuda_runtime.h>
#include <cuda_fp16.h>
#include <cstdint>
#include <cstddef>

// Problem constants
#define BB   8
#define CIN  64
#define COUT 64
#define HH   256
#define WW   256

// ---------------------------------------------------------------------------
// Device scratch (allocation-free rule: __device__ globals)
// ---------------------------------------------------------------------------
__device__ __half g_xh[(size_t)BB * HH * WW * CIN];   // 64 MB, NHWC fp16
__device__ __half g_w[(size_t)BB * 9 * COUT * CIN];   // [b][tap][co][ci] fp16

// ---------------------------------------------------------------------------
// Helpers
// ---------------------------------------------------------------------------
__device__ __forceinline__ uint32_t smem_u32(const void* p) {
    uint32_t a;
    asm("{ .reg .u64 t; cvta.to.shared.u64 t, %1; cvt.u32.u64 %0, t; }"
        : "=r"(a) : "l"(p));
    return a;
}
#define SWZ(o) ((o) ^ (((o) >> 3) & 0x70))

#define LDSM4(r0, r1, r2, r3, a) \
    asm volatile("ldmatrix.sync.aligned.m8n8.x4.shared.b16 {%0,%1,%2,%3}, [%4];" \
                 : "=r"(r0), "=r"(r1), "=r"(r2), "=r"(r3) : "r"(a))

__device__ __forceinline__ void mma16816(float* c, const uint32_t* a,
                                         const uint32_t* b) {
    asm volatile(
        "mma.sync.aligned.m16n8k16.row.col.f32.f16.f16.f32 "
        "{%0,%1,%2,%3}, {%4,%5,%6,%7}, {%8,%9}, {%0,%1,%2,%3};"
        : "+f"(c[0]), "+f"(c[1]), "+f"(c[2]), "+f"(c[3])
        : "r"(a[0]), "r"(a[1]), "r"(a[2]), "r"(a[3]), "r"(b[0]), "r"(b[1]));
}

// cp.async 16B with zero-fill when src_size = 0
#define CP_ASYNC16(dst, src, sz) \
    asm volatile("cp.async.cg.shared.global [%0], [%1], 16, %2;" \
                 :: "r"(dst), "l"(src), "r"(sz) : "memory")
#define CP_COMMIT() asm volatile("cp.async.commit_group;" ::: "memory")
#define CP_WAIT(n)  asm volatile("cp.async.wait_group %0;" :: "n"(n) : "memory")

// ---------------------------------------------------------------------------
// Fused pre-pass: blocks [0,4096) convert x NCHW fp32 -> NHWC fp16 directly
// (no smem, no syncs: 8x LDG.128 per thread, MLP=8; 4x STG.128 with every
// 128B output row fully covered by a warp).  Blocks [4096,4168) fold alpha
// into the weights.
// ---------------------------------------------------------------------------
__global__ __launch_bounds__(256)
void xwcvt_kernel(const float* __restrict__ x,
                  const float* __restrict__ weight,
                  const float* __restrict__ alpha) {
    const int blk = blockIdx.x;
    const int t = threadIdx.x;

    if (blk < 4096) {
        // ---- x convert: block = 128 px x 64 ci of one (b, h) row ----
        const int b = blk >> 9;
        const int rest = blk & 511;
        const int h = rest >> 1;
        const int w0 = (rest & 1) * 128;

        const int c8 = t & 7;          // channel octet
        const int pxg = t >> 3;        // 0..31 -> 4-px group
        const int px0 = w0 + pxg * 4;

        float4 v[8];
#pragma unroll
        for (int jj = 0; jj < 8; ++jj) {
            const int ci = c8 * 8 + jj;
            v[jj] = *(const float4*)&x[(((size_t)b * CIN + ci) * HH + h) * WW + px0];
        }
#pragma unroll
        for (int e = 0; e < 4; ++e) {
            const float* f = (const float*)v;   // v[jj] component e = f[jj*4+e]
            uint32_t q[4];
#pragma unroll
            for (int p2 = 0; p2 < 4; ++p2) {
                __half2 h2 = __float22half2_rn(
                    make_float2(f[(2 * p2) * 4 + e], f[(2 * p2 + 1) * 4 + e]));
                q[p2] = *(uint32_t*)&h2;
            }
            size_t o = (((size_t)b * HH + h) * WW + px0 + e) * CIN + c8 * 8;
            *(uint4*)&g_xh[o] = make_uint4(q[0], q[1], q[2], q[3]);
        }
    } else {
        // ---- weight fold: 72 blocks x 256 thr x 16 elems = 294912 ----
        const int blk2 = blk - 4096;
#pragma unroll
        for (int k = 0; k < 16; ++k) {
            int idx = blk2 * 4096 + t + k * 256;
            int ci = idx & 63;
            int co = (idx >> 6) & 63;
            int rest = idx >> 12;      // b*9 + tap
            float v = weight[(co * CIN + ci) * 9 + rest % 9] *
                      alpha[(rest / 9) * CIN + ci];
            g_w[(size_t)rest * 4096 + co * 64 + ci] = __float2half_rn(v);
        }
    }
}

// ---------------------------------------------------------------------------
// Main conv: fp16 mma.sync implicit GEMM, sliding window over 4 h-rows.
// Grid (2 wblk, 64 hblk, 8 b) = 1024 CTAs.  512 thr = 16 warps (4/SMSP).
// CTA step: 2 h-rows x 128 w x 64 co; 2 steps.
// A: 6 line buffers, slot l = row hbase-1+l.  Prologue issues ALL loads:
//    group1 = B(9 taps) + lines 0-3; group2 = lines 4-5.  Step 0 starts after
//    wait_group(1); step 1 after wait(0).
// B: ALL 9 tap tiles resident in smem (no per-tap syncs).
// Bias: read straight into 8 registers per thread (L2-hot), no smem trip.
// Warp: cohalf = warp&1 (32 co), wchunk = (warp>>1)&3 (32 px), hline = warp>>3.
// ---------------------------------------------------------------------------
#define ABUF     17408                 // 136 rows x 128B (130 used)
#define SM_B     (6 * ABUF)            // 104448
#define SMEM_REQ (SM_B + 9 * 8192 + 1024)
#define NTH      512

__global__ __launch_bounds__(NTH, 1)
void conv_mma_kernel(const float* __restrict__ bias, float* __restrict__ out) {
    extern __shared__ char smem_raw[];
    const uint32_t sraw = smem_u32(smem_raw);
    const uint32_t sb = (sraw + 1023) & ~1023u;

    const int tid = threadIdx.x;
    const int warp = tid >> 5;
    const int lane = tid & 31;
    const int b = blockIdx.z;
    const int hbase = blockIdx.y * 4;
    const int w0 = blockIdx.x * 128;

    const int cohalf = warp & 1;
    const int wchunk = (warp >> 1) & 3;
    const int hline = warp >> 3;

    // ---- prologue group 1: B (9 tap tiles) + A lines 0..3 ----
    {
        const char* wsrc = (const char*)g_w + (size_t)(b * 9) * 8192;
#pragma unroll
        for (int i = 0; i < 9; ++i) {
            uint32_t o = (uint32_t)(i * NTH + tid) * 16;
            CP_ASYNC16(sb + SM_B + (o & ~8191u) + SWZ(o & 8191u), wsrc + o, 16);
        }
        for (int idx = tid; idx < 4 * 1040; idx += NTH) {
            int l = idx / 1040;
            int rc = idx - l * 1040;
            int j = rc >> 3, c8 = rc & 7;
            int gh = hbase - 1 + l, gw = w0 - 1 + j;
            bool ok = (gh >= 0) && (gh < HH) && (gw >= 0) && (gw < WW);
            const char* src = ok
                ? (const char*)&g_xh[(((size_t)b * HH + gh) * WW + gw) * CIN + c8 * 8]
                : (const char*)g_xh;
            CP_ASYNC16(sb + (uint32_t)l * ABUF + SWZ((uint32_t)(j * 128 + c8 * 16)),
                       src, ok ? 16 : 0);
        }
        CP_COMMIT();
    }
    // ---- prologue group 2: A lines 4..5 (in flight through step 0) ----
    {
        for (int idx = tid; idx < 2 * 1040; idx += NTH) {
            int l = idx / 1040;
            int rc = idx - l * 1040;
            int j = rc >> 3, c8 = rc & 7;
            int gh = hbase + 3 + l, gw = w0 - 1 + j;
            bool ok = (gh < HH) && (gw >= 0) && (gw < WW);
            const char* src = ok
                ? (const char*)&g_xh[(((size_t)b * HH + gh) * WW + gw) * CIN + c8 * 8]
                : (const char*)g_xh;
            CP_ASYNC16(sb + (uint32_t)(4 + l) * ABUF +
                           SWZ((uint32_t)(j * 128 + c8 * 16)),
                       src, ok ? 16 : 0);
        }
        CP_COMMIT();
    }

    // ---- bias into registers (overlaps cp.async flight) ----
    float br0[4], br1[4];
#pragma unroll
    for (int nb = 0; nb < 4; ++nb) {
        br0[nb] = bias[cohalf * 32 + nb * 8 + (lane & 3) * 2];
        br1[nb] = bias[cohalf * 32 + nb * 8 + (lane & 3) * 2 + 1];
    }

    CP_WAIT(1);              // group 1 (B + lines 0-3) landed
    __syncthreads();

    // per-lane ldmatrix address components
    const int arow = lane & 15;
    const uint32_t acoff = (uint32_t)(lane >> 4) * 16;
    const int brow = (lane & 7) + (lane >> 4) * 8;
    const uint32_t bcoff = (uint32_t)((lane >> 3) & 1) * 16;

#pragma unroll
    for (int s = 0; s < 2; ++s) {
        const int h0 = hbase + 2 * s;

        // ---- accumulators: bias-initialized from registers ----
        float acc[2][4][4];
#pragma unroll
        for (int nb = 0; nb < 4; ++nb) {
#pragma unroll
            for (int mh = 0; mh < 2; ++mh) {
                acc[mh][nb][0] = br0[nb]; acc[mh][nb][1] = br1[nb];
                acc[mh][nb][2] = br0[nb]; acc[mh][nb][3] = br1[nb];
            }
        }

        // ---- tap loop: everything resident, zero syncs ----
#pragma unroll
        for (int tap = 0; tap < 9; ++tap) {
            const int kh = tap / 3, kw = tap - kh * 3;
            const uint32_t aA = sb + (uint32_t)(2 * s + hline + kh) * ABUF;
            const uint32_t bB = sb + SM_B + (uint32_t)tap * 8192;
            const int r0 = wchunk * 32 + kw + arow;     // + mh*16, max 129

#pragma unroll
            for (int kc = 0; kc < 4; ++kc) {
                const uint32_t co = (uint32_t)kc * 32 + acoff;
                uint32_t ah[2][4];
#pragma unroll
                for (int mh = 0; mh < 2; ++mh) {
                    uint32_t off = SWZ((uint32_t)((r0 + mh * 16) * 128) + co);
                    LDSM4(ah[mh][0], ah[mh][1], ah[mh][2], ah[mh][3], aA + off);
                }
#pragma unroll
                for (int nb2 = 0; nb2 < 2; ++nb2) {
                    uint32_t boff = SWZ(
                        (uint32_t)((cohalf * 32 + nb2 * 16 + brow) * 128) +
                        (uint32_t)kc * 32 + bcoff);
                    uint32_t bh[4];
                    LDSM4(bh[0], bh[1], bh[2], bh[3], bB + boff);
#pragma unroll
                    for (int mh = 0; mh < 2; ++mh) {
                        mma16816(acc[mh][2 * nb2],     ah[mh], bh);
                        mma16816(acc[mh][2 * nb2 + 1], ah[mh], bh + 2);
                    }
                }
            }
        }

        // ---- epilogue for this step ----
        const int hgl = h0 + hline;
#pragma unroll
        for (int mh = 0; mh < 2; ++mh) {
            const int wgl = w0 + wchunk * 32 + mh * 16 + (lane >> 2);
#pragma unroll
            for (int nb = 0; nb < 4; ++nb) {
                const int n0 = cohalf * 32 + nb * 8 + (lane & 3) * 2;
                float* p = out + (((size_t)b * COUT + n0) * HH + hgl) * WW + wgl;
                p[0] = acc[mh][nb][0];
                p[(size_t)HH * WW] = acc[mh][nb][1];
                p[8] = acc[mh][nb][2];
                p[(size_t)HH * WW + 8] = acc[mh][nb][3];
            }
        }

        if (s == 0) {
            CP_WAIT(0);      // lines 4-5 landed (overlapped with step-0 MMAs)
            __syncthreads();
        }
    }
}

// ---------------------------------------------------------------------------
// Launch. Inputs: x, alpha, weight, bias. Output: float32 NCHW.
// ---------------------------------------------------------------------------
extern "C" void kernel_launch(void* const* d_in, const int* in_sizes, int n_in,
                              void* d_out, int out_size) {
    const float* x      = (const float*)d_in[0];
    const float* alpha  = (const float*)d_in[1];
    const float* weight = (const float*)d_in[2];
    const float* bias   = (const float*)d_in[3];
    float* out = (float*)d_out;
    (void)in_sizes; (void)n_in; (void)out_size;

    cudaFuncSetAttribute(conv_mma_kernel,
                         cudaFuncAttributeMaxDynamicSharedMemorySize, SMEM_REQ);

    xwcvt_kernel<<<4096 + 72, 256>>>(x, weight, alpha);
    conv_mma_kernel<<<dim3(2, 64, BB), NTH, SMEM_REQ>>>(bias, out);
}

// round 17
// speedup vs baseline: 1.4367x; 1.4367x over previous
#include <cuda_runtime.h>
#include <cuda_fp16.h>
#include <cstdint>
#include <cstddef>

// Problem constants
#define BB   8
#define CIN  64
#define COUT 64
#define HH   256
#define WW   256

// ---------------------------------------------------------------------------
// Device scratch (allocation-free rule: __device__ globals)
// ---------------------------------------------------------------------------
__device__ __half g_xh[(size_t)BB * HH * WW * CIN];   // 64 MB, NHWC fp16
__device__ __half g_w[(size_t)BB * 9 * COUT * CIN];   // [b][tap][co][ci] fp16

// ---------------------------------------------------------------------------
// Helpers
// ---------------------------------------------------------------------------
__device__ __forceinline__ uint32_t smem_u32(const void* p) {
    uint32_t a;
    asm("{ .reg .u64 t; cvta.to.shared.u64 t, %1; cvt.u32.u64 %0, t; }"
        : "=r"(a) : "l"(p));
    return a;
}
#define SWZ(o) ((o) ^ (((o) >> 3) & 0x70))

#define LDSM4(r0, r1, r2, r3, a) \
    asm volatile("ldmatrix.sync.aligned.m8n8.x4.shared.b16 {%0,%1,%2,%3}, [%4];" \
                 : "=r"(r0), "=r"(r1), "=r"(r2), "=r"(r3) : "r"(a))

__device__ __forceinline__ void mma16816(float* c, const uint32_t* a,
                                         const uint32_t* b) {
    asm volatile(
        "mma.sync.aligned.m16n8k16.row.col.f32.f16.f16.f32 "
        "{%0,%1,%2,%3}, {%4,%5,%6,%7}, {%8,%9}, {%0,%1,%2,%3};"
        : "+f"(c[0]), "+f"(c[1]), "+f"(c[2]), "+f"(c[3])
        : "r"(a[0]), "r"(a[1]), "r"(a[2]), "r"(a[3]), "r"(b[0]), "r"(b[1]));
}

// cp.async 16B with zero-fill when src_size = 0
#define CP_ASYNC16(dst, src, sz) \
    asm volatile("cp.async.cg.shared.global [%0], [%1], 16, %2;" \
                 :: "r"(dst), "l"(src), "r"(sz) : "memory")
#define CP_COMMIT() asm volatile("cp.async.commit_group;" ::: "memory")
#define CP_WAIT(n)  asm volatile("cp.async.wait_group %0;" :: "n"(n) : "memory")

// ---------------------------------------------------------------------------
// Fused pre-pass. Blocks [0,2048): staged x convert (one (b,h) row each,
// same algorithm as the measured-34.7us version).  Blocks [2048,2120):
// alpha-fold the weights.  One launch instead of two.
// ---------------------------------------------------------------------------
__global__ __launch_bounds__(256)
void xwcvt_kernel(const float* __restrict__ x,
                  const float* __restrict__ weight,
                  const float* __restrict__ alpha) {
    const int blk = blockIdx.x;
    const int t = threadIdx.x;

    if (blk >= 2048) {
        // ---- weight fold: 72 blocks x 256 thr x 16 elems = 294912 ----
        const int blk2 = blk - 2048;
#pragma unroll
        for (int k = 0; k < 16; ++k) {
            int idx = blk2 * 4096 + t + k * 256;
            int ci = idx & 63;
            int co = (idx >> 6) & 63;
            int rest = idx >> 12;      // b*9 + tap
            float v = weight[(co * CIN + ci) * 9 + rest % 9] *
                      alpha[(rest / 9) * CIN + ci];
            g_w[(size_t)rest * 4096 + co * 64 + ci] = __float2half_rn(v);
        }
        return;
    }

    // ---- x convert: staged transpose through swizzled smem tile ----
    __shared__ float tile[64 * 64];
    const int b = blk >> 8;
    const int h = blk & 255;
    for (int w0 = 0; w0 < WW; w0 += 64) {
        // phase 1: LDG.128 coalesced, STS.128 swizzled
        {
            const int cil = t >> 4;        // 0..15
            const int wq = (t & 15) * 4;   // 0..60
#pragma unroll
            for (int k = 0; k < 4; ++k) {
                const int ci = cil + k * 16;
                float4 v = *(const float4*)&x[(((size_t)b * CIN + ci) * HH + h) * WW +
                                              w0 + wq];
                const int sx = ((ci & 7) ^ ((ci >> 3) & 7)) << 3;  // float units
                *(float4*)&tile[ci * 64 + (wq ^ sx)] = v;
            }
        }
        __syncthreads();
        // phase 2: transpose-read 8 ci at fixed pixel, pack, STG.128
        {
            const int c8 = t & 7;
            const int p0 = t >> 3;         // 0..31
#pragma unroll
            for (int m = 0; m < 2; ++m) {
                const int p = p0 + m * 32;
                uint32_t q[4];
#pragma unroll
                for (int jj = 0; jj < 4; ++jj) {
                    const int ci0 = c8 * 8 + jj * 2;
                    const int sx0 = (((ci0 & 7) ^ c8) << 3);
                    const int sx1 = ((((ci0 + 1) & 7) ^ c8) << 3);
                    float v0 = tile[ci0 * 64 + (p ^ sx0)];
                    float v1 = tile[(ci0 + 1) * 64 + (p ^ sx1)];
                    __half2 h2 = __float22half2_rn(make_float2(v0, v1));
                    q[jj] = *(uint32_t*)&h2;
                }
                size_t o = (((size_t)b * HH + h) * WW + w0 + p) * CIN + c8 * 8;
                *(uint4*)&g_xh[o] = make_uint4(q[0], q[1], q[2], q[3]);
            }
        }
        __syncthreads();
    }
}

// ---------------------------------------------------------------------------
// Main conv: fp16 mma.sync implicit GEMM, sliding window over 4 h-rows.
// (R14 configuration verbatim — smem bias; NO extra kernel-lifetime registers:
//  the 128-reg cap spills otherwise, proven twice.)
// Grid (2 wblk, 64 hblk, 8 b) = 1024 CTAs.  512 thr = 16 warps (4/SMSP).
// A: 6 line buffers; prologue group1 = B(9 taps)+lines 0-3, group2 = lines 4-5.
// B: ALL 9 tap tiles resident; zero per-tap syncs.
// Warp: cohalf = warp&1 (32 co), wchunk = (warp>>1)&3 (32 px), hline = warp>>3.
// ---------------------------------------------------------------------------
#define ABUF     17408                 // 136 rows x 128B (130 used)
#define SM_B     (6 * ABUF)            // 104448
#define SM_BIAS  (SM_B + 9 * 8192)     // 178176
#define SMEM_REQ (SM_BIAS + 256 + 1024)
#define NTH      512

__global__ __launch_bounds__(NTH, 1)
void conv_mma_kernel(const float* __restrict__ bias, float* __restrict__ out) {
    extern __shared__ char smem_raw[];
    const uint32_t sraw = smem_u32(smem_raw);
    const uint32_t sb = (sraw + 1023) & ~1023u;
    char* g = smem_raw + (sb - sraw);

    const int tid = threadIdx.x;
    const int warp = tid >> 5;
    const int lane = tid & 31;
    const int b = blockIdx.z;
    const int hbase = blockIdx.y * 4;
    const int w0 = blockIdx.x * 128;

    const int cohalf = warp & 1;
    const int wchunk = (warp >> 1) & 3;
    const int hline = warp >> 3;

    if (tid < 64) ((float*)(g + SM_BIAS))[tid] = bias[tid];

    // ---- prologue group 1: B (9 tap tiles) + A lines 0..3 ----
    {
        const char* wsrc = (const char*)g_w + (size_t)(b * 9) * 8192;
#pragma unroll
        for (int i = 0; i < 9; ++i) {
            uint32_t o = (uint32_t)(i * NTH + tid) * 16;
            CP_ASYNC16(sb + SM_B + (o & ~8191u) + SWZ(o & 8191u), wsrc + o, 16);
        }
        for (int idx = tid; idx < 4 * 1040; idx += NTH) {
            int l = idx / 1040;
            int rc = idx - l * 1040;
            int j = rc >> 3, c8 = rc & 7;
            int gh = hbase - 1 + l, gw = w0 - 1 + j;
            bool ok = (gh >= 0) && (gh < HH) && (gw >= 0) && (gw < WW);
            const char* src = ok
                ? (const char*)&g_xh[(((size_t)b * HH + gh) * WW + gw) * CIN + c8 * 8]
                : (const char*)g_xh;
            CP_ASYNC16(sb + (uint32_t)l * ABUF + SWZ((uint32_t)(j * 128 + c8 * 16)),
                       src, ok ? 16 : 0);
        }
        CP_COMMIT();
    }
    // ---- prologue group 2: A lines 4..5 (in flight through step 0) ----
    {
        for (int idx = tid; idx < 2 * 1040; idx += NTH) {
            int l = idx / 1040;
            int rc = idx - l * 1040;
            int j = rc >> 3, c8 = rc & 7;
            int gh = hbase + 3 + l, gw = w0 - 1 + j;
            bool ok = (gh < HH) && (gw >= 0) && (gw < WW);
            const char* src = ok
                ? (const char*)&g_xh[(((size_t)b * HH + gh) * WW + gw) * CIN + c8 * 8]
                : (const char*)g_xh;
            CP_ASYNC16(sb + (uint32_t)(4 + l) * ABUF +
                           SWZ((uint32_t)(j * 128 + c8 * 16)),
                       src, ok ? 16 : 0);
        }
        CP_COMMIT();
    }
    CP_WAIT(1);              // group 1 (B + lines 0-3) landed
    __syncthreads();

    const float* biasS = (const float*)(g + SM_BIAS);

    // per-lane ldmatrix address components
    const int arow = lane & 15;
    const uint32_t acoff = (uint32_t)(lane >> 4) * 16;
    const int brow = (lane & 7) + (lane >> 4) * 8;
    const uint32_t bcoff = (uint32_t)((lane >> 3) & 1) * 16;

#pragma unroll
    for (int s = 0; s < 2; ++s) {
        const int h0 = hbase + 2 * s;

        // ---- accumulators: bias-initialized from smem ----
        float acc[2][4][4];
#pragma unroll
        for (int nb = 0; nb < 4; ++nb) {
            float b0 = biasS[cohalf * 32 + nb * 8 + (lane & 3) * 2];
            float b1 = biasS[cohalf * 32 + nb * 8 + (lane & 3) * 2 + 1];
#pragma unroll
            for (int mh = 0; mh < 2; ++mh) {
                acc[mh][nb][0] = b0; acc[mh][nb][1] = b1;
                acc[mh][nb][2] = b0; acc[mh][nb][3] = b1;
            }
        }

        // ---- tap loop: everything resident, zero syncs ----
#pragma unroll
        for (int tap = 0; tap < 9; ++tap) {
            const int kh = tap / 3, kw = tap - kh * 3;
            const uint32_t aA = sb + (uint32_t)(2 * s + hline + kh) * ABUF;
            const uint32_t bB = sb + SM_B + (uint32_t)tap * 8192;
            const int r0 = wchunk * 32 + kw + arow;     // + mh*16, max 129

#pragma unroll
            for (int kc = 0; kc < 4; ++kc) {
                const uint32_t co = (uint32_t)kc * 32 + acoff;
                uint32_t ah[2][4];
#pragma unroll
                for (int mh = 0; mh < 2; ++mh) {
                    uint32_t off = SWZ((uint32_t)((r0 + mh * 16) * 128) + co);
                    LDSM4(ah[mh][0], ah[mh][1], ah[mh][2], ah[mh][3], aA + off);
                }
#pragma unroll
                for (int nb2 = 0; nb2 < 2; ++nb2) {
                    uint32_t boff = SWZ(
                        (uint32_t)((cohalf * 32 + nb2 * 16 + brow) * 128) +
                        (uint32_t)kc * 32 + bcoff);
                    uint32_t bh[4];
                    LDSM4(bh[0], bh[1], bh[2], bh[3], bB + boff);
#pragma unroll
                    for (int mh = 0; mh < 2; ++mh) {
                        mma16816(acc[mh][2 * nb2],     ah[mh], bh);
                        mma16816(acc[mh][2 * nb2 + 1], ah[mh], bh + 2);
                    }
                }
            }
        }

        // ---- epilogue for this step ----
        const int hgl = h0 + hline;
#pragma unroll
        for (int mh = 0; mh < 2; ++mh) {
            const int wgl = w0 + wchunk * 32 + mh * 16 + (lane >> 2);
#pragma unroll
            for (int nb = 0; nb < 4; ++nb) {
                const int n0 = cohalf * 32 + nb * 8 + (lane & 3) * 2;
                float* p = out + (((size_t)b * COUT + n0) * HH + hgl) * WW + wgl;
                p[0] = acc[mh][nb][0];
                p[(size_t)HH * WW] = acc[mh][nb][1];
                p[8] = acc[mh][nb][2];
                p[(size_t)HH * WW + 8] = acc[mh][nb][3];
            }
        }

        if (s == 0) {
            CP_WAIT(0);      // lines 4-5 landed (overlapped with step-0 MMAs)
            __syncthreads();
        }
    }
}

// ---------------------------------------------------------------------------
// Launch. Inputs: x, alpha, weight, bias. Output: float32 NCHW.
// ---------------------------------------------------------------------------
extern "C" void kernel_launch(void* const* d_in, const int* in_sizes, int n_in,
                              void* d_out, int out_size) {
    const float* x      = (const float*)d_in[0];
    const float* alpha  = (const float*)d_in[1];
    const float* weight = (const float*)d_in[2];
    const float* bias   = (const float*)d_in[3];
    float* out = (float*)d_out;
    (void)in_sizes; (void)n_in; (void)out_size;

    cudaFuncSetAttribute(conv_mma_kernel,
                         cudaFuncAttributeMaxDynamicSharedMemorySize, SMEM_REQ);

    xwcvt_kernel<<<2048 + 72, 256>>>(x, weight, alpha);
    conv_mma_kernel<<<dim3(2, 64, BB), NTH, SMEM_REQ>>>(bias, out);
}